// round 1
// baseline (speedup 1.0000x reference)
#include <cuda_runtime.h>

// Problem constants
constexpr int B    = 8;
constexpr int C    = 256;
constexpr int L    = 1024;     // 32*32
constexpr int NH   = 8;
constexpr int DK   = 32;
constexpr int DV   = 32;
constexpr int OUTC = 256;
constexpr int TBL  = 63 * 63;  // 3969 relative-bias table entries

// Scratch (device globals — no allocation allowed)
__device__ float g_q[(size_t)B * NH * L * DK];     // [b][h][l][d]
__device__ float g_k[(size_t)B * NH * L * DK];
__device__ float g_v[(size_t)B * NH * L * DV];
__device__ float g_attn[(size_t)B * L * NH * DV];  // [b][l][h*DV+d]

// ---------------------------------------------------------------------------
// Kernel 1: QKV projections.  out = x[b]^T @ W  (x[b] is (C, L) row-major)
// Tiles: BM=128, BN=64, BK=16; 256 threads, 8x4 per thread.
// Output written directly in [b][h][l][d] layout.
// ---------------------------------------------------------------------------
__global__ __launch_bounds__(256) void qkv_gemm(
    const float* __restrict__ x,
    const float* __restrict__ Qw,
    const float* __restrict__ Kw,
    const float* __restrict__ Vw)
{
    __shared__ float As[16][128];  // As[k][m] (A^T tile)
    __shared__ float Ws[16][64];   // Ws[k][n]

    const int bz    = blockIdx.z;
    const int b     = bz / 3;
    const int which = bz % 3;
    const float* A  = x + (size_t)b * C * L;                 // (C, L)
    const float* Wm = (which == 0) ? Qw : (which == 1) ? Kw : Vw;
    float* outg     = (which == 0) ? g_q : (which == 1) ? g_k : g_v;

    const int m0  = blockIdx.x * 128;
    const int n0  = blockIdx.y * 64;
    const int tid = threadIdx.x;
    const int tm  = tid / 16;   // 0..15 -> 8 rows each
    const int tn  = tid % 16;   // 0..15 -> 4 cols each

    float acc[8][4] = {};

    for (int k0 = 0; k0 < C; k0 += 16) {
        // Load A^T tile: As[k][m] = A[(k0+k)*L + m0+m]   (coalesced over m)
#pragma unroll
        for (int it = 0; it < 2; it++) {
            int s  = tid + it * 256;      // 512 float4 slots
            int kk = s >> 5;              // 32 float4 per 128-wide row
            int m4 = s & 31;
            *(float4*)&As[kk][m4 * 4] =
                *(const float4*)&A[(size_t)(k0 + kk) * L + m0 + m4 * 4];
        }
        // Load W tile
        {
            int kk = tid >> 4;
            int n4 = tid & 15;
            *(float4*)&Ws[kk][n4 * 4] =
                *(const float4*)&Wm[(size_t)(k0 + kk) * (NH * DK) + n0 + n4 * 4];
        }
        __syncthreads();

#pragma unroll
        for (int kk = 0; kk < 16; kk++) {
            float ra[8], rb[4];
            *(float4*)&ra[0] = *(float4*)&As[kk][tm * 8];
            *(float4*)&ra[4] = *(float4*)&As[kk][tm * 8 + 4];
            *(float4*)&rb[0] = *(float4*)&Ws[kk][tn * 4];
#pragma unroll
            for (int i = 0; i < 8; i++)
#pragma unroll
                for (int j = 0; j < 4; j++)
                    acc[i][j] += ra[i] * rb[j];
        }
        __syncthreads();
    }

    // Store to [b][h][l][d]; each thread's 4 cols stay within one head (4 | 32)
    const int n  = n0 + tn * 4;
    const int h  = n >> 5;
    const int d0 = n & 31;
    float* dst = outg + ((size_t)(b * NH + h) * L) * DK;
#pragma unroll
    for (int i = 0; i < 8; i++) {
        int m = m0 + tm * 8 + i;
        *(float4*)&dst[(size_t)m * DK + d0] = *(float4*)&acc[i][0];
    }
}

// ---------------------------------------------------------------------------
// Kernel 2: flash attention per (b,h), 64 query rows per block, Bc=32 tiles.
// rel_bias table staged in smem; online softmax with 16-lane shuffles.
// ---------------------------------------------------------------------------
__global__ __launch_bounds__(256) void attn_kernel(
    const float* __restrict__ rel_bias,
    const int*   __restrict__ rel_idx)
{
    __shared__ float Qs[64][33];
    __shared__ float Ks[32][33];
    __shared__ float Vs[32][33];
    __shared__ float Ps[64][33];
    __shared__ float bias_s[TBL];

    const int bh = blockIdx.y;       // b*NH + h
    const int h  = bh & 7;
    const float* q = g_q + (size_t)bh * L * DK;
    const float* k = g_k + (size_t)bh * L * DK;
    const float* v = g_v + (size_t)bh * L * DV;

    const int i0  = blockIdx.x * 64;
    const int tid = threadIdx.x;
    const int ty  = tid / 16;   // 0..15 -> 4 query rows each
    const int tx  = tid % 16;   // 0..15 -> 2 key cols each

    for (int idx = tid; idx < TBL; idx += 256)
        bias_s[idx] = rel_bias[(size_t)h * TBL + idx];
    for (int idx = tid; idx < 64 * 32; idx += 256)
        Qs[idx >> 5][idx & 31] = q[(size_t)i0 * DK + idx];

    float m_i[4], l_i[4], o[4][2];
#pragma unroll
    for (int i = 0; i < 4; i++) {
        m_i[i] = -1e30f; l_i[i] = 0.f; o[i][0] = 0.f; o[i][1] = 0.f;
    }
    __syncthreads();

    for (int jt = 0; jt < L / 32; jt++) {
        const int j0 = jt * 32;
        for (int idx = tid; idx < 32 * 32; idx += 256) {
            Ks[idx >> 5][idx & 31] = k[(size_t)j0 * DK + idx];
            Vs[idx >> 5][idx & 31] = v[(size_t)j0 * DV + idx];
        }
        __syncthreads();

        // S = Q K^T
        float s[4][2] = {};
#pragma unroll
        for (int d = 0; d < 32; d++) {
            float kv0 = Ks[tx * 2][d];
            float kv1 = Ks[tx * 2 + 1][d];
#pragma unroll
            for (int i = 0; i < 4; i++) {
                float qv = Qs[ty * 4 + i][d];
                s[i][0] += qv * kv0;
                s[i][1] += qv * kv1;
            }
        }
        // + relative bias (gather index from gmem/L2, value from smem)
#pragma unroll
        for (int i = 0; i < 4; i++) {
            const int* ri = rel_idx + (size_t)(i0 + ty * 4 + i) * L + j0 + tx * 2;
            s[i][0] += bias_s[ri[0]];
            s[i][1] += bias_s[ri[1]];
        }
        // online softmax update
#pragma unroll
        for (int i = 0; i < 4; i++) {
            float mx = fmaxf(s[i][0], s[i][1]);
#pragma unroll
            for (int off = 8; off; off >>= 1)
                mx = fmaxf(mx, __shfl_xor_sync(0xffffffffu, mx, off, 16));
            float m_new = fmaxf(m_i[i], mx);
            float scale = __expf(m_i[i] - m_new);
            float p0 = __expf(s[i][0] - m_new);
            float p1 = __expf(s[i][1] - m_new);
            float rs = p0 + p1;
#pragma unroll
            for (int off = 8; off; off >>= 1)
                rs += __shfl_xor_sync(0xffffffffu, rs, off, 16);
            l_i[i] = l_i[i] * scale + rs;
            m_i[i] = m_new;
            o[i][0] *= scale; o[i][1] *= scale;
            Ps[ty * 4 + i][tx * 2]     = p0;
            Ps[ty * 4 + i][tx * 2 + 1] = p1;
        }
        __syncthreads();

        // O += P V
#pragma unroll
        for (int kk = 0; kk < 32; kk++) {
            float v0 = Vs[kk][tx * 2];
            float v1 = Vs[kk][tx * 2 + 1];
#pragma unroll
            for (int i = 0; i < 4; i++) {
                float p = Ps[ty * 4 + i][kk];
                o[i][0] += p * v0;
                o[i][1] += p * v1;
            }
        }
        __syncthreads();
    }

    const int b = bh >> 3;
#pragma unroll
    for (int i = 0; i < 4; i++) {
        float inv = 1.f / l_i[i];
        int row = i0 + ty * 4 + i;
        float* dst = g_attn + ((size_t)(b * L + row)) * (NH * DV) + h * DV + tx * 2;
        dst[0] = o[i][0] * inv;
        dst[1] = o[i][1] * inv;
    }
}

// ---------------------------------------------------------------------------
// Kernel 3: FF projection + bias, output transposed to (B, OUTC, L).
// A = g_attn (8192, 256) row-major; tiles 128x64x16; 8x4 per thread.
// ---------------------------------------------------------------------------
__global__ __launch_bounds__(256) void ff_kernel(
    const float* __restrict__ ffw,
    const float* __restrict__ ffb,
    float* __restrict__ out)
{
    __shared__ float As[16][132];  // As[k][m], transposed on load (padded)
    __shared__ float Ws[16][64];

    const int m0  = blockIdx.x * 128;  // row in (B*L)
    const int n0  = blockIdx.y * 64;
    const int tid = threadIdx.x;
    const int tm  = tid / 16;
    const int tn  = tid % 16;

    float acc[8][4] = {};
    const float* A = g_attn;

    for (int k0 = 0; k0 < NH * DV; k0 += 16) {
        // Load A tile with transpose: coalesced reads over k
#pragma unroll
        for (int it = 0; it < 2; it++) {
            int s  = tid + it * 256;    // 512 float4 slots (128 rows x 4)
            int m  = s >> 2;
            int k4 = s & 3;
            float4 val = *(const float4*)&A[(size_t)(m0 + m) * (NH * DV) + k0 + k4 * 4];
            As[k4 * 4 + 0][m] = val.x;
            As[k4 * 4 + 1][m] = val.y;
            As[k4 * 4 + 2][m] = val.z;
            As[k4 * 4 + 3][m] = val.w;
        }
        {
            int kk = tid >> 4;
            int n4 = tid & 15;
            *(float4*)&Ws[kk][n4 * 4] =
                *(const float4*)&ffw[(size_t)(k0 + kk) * OUTC + n0 + n4 * 4];
        }
        __syncthreads();

#pragma unroll
        for (int kk = 0; kk < 16; kk++) {
            float ra[8], rb[4];
            *(float4*)&ra[0] = *(float4*)&As[kk][tm * 8];
            *(float4*)&ra[4] = *(float4*)&As[kk][tm * 8 + 4];
            *(float4*)&rb[0] = *(float4*)&Ws[kk][tn * 4];
#pragma unroll
            for (int i = 0; i < 8; i++)
#pragma unroll
                for (int j = 0; j < 4; j++)
                    acc[i][j] += ra[i] * rb[j];
        }
        __syncthreads();
    }

    // Store transposed: out[(b*OUTC + n)*L + l] + bias
    const int b  = m0 >> 10;
    const int l0 = m0 & 1023;
#pragma unroll
    for (int j = 0; j < 4; j++) {
        int n = n0 + tn * 4 + j;
        float bias = ffb[n];
        float* dst = out + ((size_t)(b * OUTC + n)) * L + l0 + tm * 8;
        float tmp[8];
#pragma unroll
        for (int i = 0; i < 8; i++) tmp[i] = acc[i][j] + bias;
        *(float4*)&dst[0] = *(float4*)&tmp[0];
        *(float4*)&dst[4] = *(float4*)&tmp[4];
    }
}

// ---------------------------------------------------------------------------
extern "C" void kernel_launch(void* const* d_in, const int* in_sizes, int n_in,
                              void* d_out, int out_size)
{
    const float* x        = (const float*)d_in[0];
    const float* Qw       = (const float*)d_in[1];
    const float* Kw       = (const float*)d_in[2];
    const float* Vw       = (const float*)d_in[3];
    const float* ffw      = (const float*)d_in[4];
    const float* ffb      = (const float*)d_in[5];
    const float* rel_bias = (const float*)d_in[6];
    const int*   rel_idx  = (const int*)d_in[7];
    float* out = (float*)d_out;

    qkv_gemm<<<dim3(L / 128, (NH * DK) / 64, B * 3), 256>>>(x, Qw, Kw, Vw);
    attn_kernel<<<dim3(L / 64, B * NH), 256>>>(rel_bias, rel_idx);
    ff_kernel<<<dim3((B * L) / 128, OUTC / 64, 1), 256>>>(ffw, ffb, out);
}

// round 2
// speedup vs baseline: 2.7046x; 2.7046x over previous
#include <cuda_runtime.h>

// Problem constants
constexpr int B    = 8;
constexpr int C    = 256;
constexpr int L    = 1024;     // 32*32
constexpr int NH   = 8;
constexpr int DK   = 32;
constexpr int DV   = 32;
constexpr int OUTC = 256;
constexpr int TBL  = 63 * 63;  // 3969 relative-bias table entries
constexpr int BIAS_STAGE = 2080;  // idx = j - i + 1056 ∈ [33, 2079]

// Scratch (device globals — no allocation allowed)
__device__ float g_q[(size_t)B * NH * L * DK];     // [b][h][l][d]
__device__ float g_k[(size_t)B * NH * L * DK];
__device__ float g_v[(size_t)B * NH * L * DV];
__device__ float g_attn[(size_t)B * L * NH * DV];  // [b][l][h*DV+d]

// ---------------------------------------------------------------------------
// Kernel 1: QKV projections (unchanged, known-good fp32).
// ---------------------------------------------------------------------------
__global__ __launch_bounds__(256) void qkv_gemm(
    const float* __restrict__ x,
    const float* __restrict__ Qw,
    const float* __restrict__ Kw,
    const float* __restrict__ Vw)
{
    __shared__ float As[16][128];
    __shared__ float Ws[16][64];

    const int bz    = blockIdx.z;
    const int b     = bz / 3;
    const int which = bz % 3;
    const float* A  = x + (size_t)b * C * L;
    const float* Wm = (which == 0) ? Qw : (which == 1) ? Kw : Vw;
    float* outg     = (which == 0) ? g_q : (which == 1) ? g_k : g_v;

    const int m0  = blockIdx.x * 128;
    const int n0  = blockIdx.y * 64;
    const int tid = threadIdx.x;
    const int tm  = tid / 16;
    const int tn  = tid % 16;

    float acc[8][4] = {};

    for (int k0 = 0; k0 < C; k0 += 16) {
#pragma unroll
        for (int it = 0; it < 2; it++) {
            int s  = tid + it * 256;
            int kk = s >> 5;
            int m4 = s & 31;
            *(float4*)&As[kk][m4 * 4] =
                *(const float4*)&A[(size_t)(k0 + kk) * L + m0 + m4 * 4];
        }
        {
            int kk = tid >> 4;
            int n4 = tid & 15;
            *(float4*)&Ws[kk][n4 * 4] =
                *(const float4*)&Wm[(size_t)(k0 + kk) * (NH * DK) + n0 + n4 * 4];
        }
        __syncthreads();

#pragma unroll
        for (int kk = 0; kk < 16; kk++) {
            float ra[8], rb[4];
            *(float4*)&ra[0] = *(float4*)&As[kk][tm * 8];
            *(float4*)&ra[4] = *(float4*)&As[kk][tm * 8 + 4];
            *(float4*)&rb[0] = *(float4*)&Ws[kk][tn * 4];
#pragma unroll
            for (int i = 0; i < 8; i++)
#pragma unroll
                for (int j = 0; j < 4; j++)
                    acc[i][j] += ra[i] * rb[j];
        }
        __syncthreads();
    }

    const int n  = n0 + tn * 4;
    const int h  = n >> 5;
    const int d0 = n & 31;
    float* dst = outg + ((size_t)(b * NH + h) * L) * DK;
#pragma unroll
    for (int i = 0; i < 8; i++) {
        int m = m0 + tm * 8 + i;
        *(float4*)&dst[(size_t)m * DK + d0] = *(float4*)&acc[i][0];
    }
}

// ---------------------------------------------------------------------------
// tf32 helpers
// ---------------------------------------------------------------------------
__device__ __forceinline__ unsigned f2tf32(float x) {
    unsigned r;
    asm("cvt.rna.tf32.f32 %0, %1;" : "=r"(r) : "f"(x));
    return r;
}

__device__ __forceinline__ void mma_tf32(float c[4], const unsigned a[4],
                                         unsigned b0, unsigned b1) {
    asm("mma.sync.aligned.m16n8k8.row.col.f32.tf32.tf32.f32 "
        "{%0,%1,%2,%3}, {%4,%5,%6,%7}, {%8,%9}, {%0,%1,%2,%3};"
        : "+f"(c[0]), "+f"(c[1]), "+f"(c[2]), "+f"(c[3])
        : "r"(a[0]), "r"(a[1]), "r"(a[2]), "r"(a[3]), "r"(b0), "r"(b1));
}

// ---------------------------------------------------------------------------
// Kernel 2: flash attention with mma.sync tf32.
//   Br=128 (8 warps x 16 rows), Bc=64. QK^T uses 3xTF32 split (fp32-level
//   accuracy); PV uses plain tf32. Bias is Toeplitz: bias[i,j]=rel_bias[h][j-i+1056].
//   k-index permutation (logical c <-> physical 2c) makes all frags LDS.64.
// ---------------------------------------------------------------------------
__global__ __launch_bounds__(256) void attn_mma(const float* __restrict__ rel_bias)
{
    constexpr int KP = 36;  // kh/kl row pitch (floats, even)
    constexpr int VP = 66;  // vt row pitch
    __shared__ float bias_s[BIAS_STAGE];
    __shared__ float kh_s[64 * KP];
    __shared__ float kl_s[64 * KP];
    __shared__ float vt_s[32 * VP];

    const int bh = blockIdx.y;
    const int h  = bh & 7;
    const int b  = bh >> 3;
    const float* q = g_q + (size_t)bh * L * DK;
    const float* k = g_k + (size_t)bh * L * DK;
    const float* v = g_v + (size_t)bh * L * DV;

    const int tid  = threadIdx.x;
    const int warp = tid >> 5;
    const int lane = tid & 31;
    const int g    = lane >> 2;
    const int c    = lane & 3;
    const int ibase = blockIdx.x * 128 + warp * 16;

    for (int i = tid; i < BIAS_STAGE; i += 256)
        bias_s[i] = rel_bias[(size_t)h * TBL + i];

    // Q fragments (hi/lo split), persistent in registers.
    unsigned qh[4][4], ql[4][4];
    {
        const float* q0 = q + (size_t)(ibase + g) * DK;
        const float* q1 = q0 + 8 * DK;
#pragma unroll
        for (int kt = 0; kt < 4; kt++) {
            float2 f0 = *(const float2*)(q0 + kt * 8 + 2 * c);
            float2 f1 = *(const float2*)(q1 + kt * 8 + 2 * c);
            qh[kt][0] = f2tf32(f0.x);
            qh[kt][2] = f2tf32(f0.y);
            qh[kt][1] = f2tf32(f1.x);
            qh[kt][3] = f2tf32(f1.y);
            ql[kt][0] = f2tf32(f0.x - __uint_as_float(qh[kt][0]));
            ql[kt][2] = f2tf32(f0.y - __uint_as_float(qh[kt][2]));
            ql[kt][1] = f2tf32(f1.x - __uint_as_float(qh[kt][1]));
            ql[kt][3] = f2tf32(f1.y - __uint_as_float(qh[kt][3]));
        }
    }

    float m0 = -1e30f, m1 = -1e30f, l0 = 0.f, l1 = 0.f;
    float o[4][4] = {};

    for (int j0 = 0; j0 < L; j0 += 64) {
        __syncthreads();
        // Stage K (hi/lo split) and V (transposed, tf32-rounded).
#pragma unroll
        for (int it = 0; it < 2; it++) {
            int idx = tid + it * 256;      // 0..511
            int j   = idx >> 3;            // 0..63
            int d4  = idx & 7;             // float4 index
            float4 kk = *(const float4*)(k + (size_t)(j0 + j) * DK + d4 * 4);
            float ka[4] = {kk.x, kk.y, kk.z, kk.w};
            float hv[4], lv[4];
#pragma unroll
            for (int e = 0; e < 4; e++) {
                hv[e] = __uint_as_float(f2tf32(ka[e]));
                lv[e] = __uint_as_float(f2tf32(ka[e] - hv[e]));
            }
            *(float4*)&kh_s[j * KP + d4 * 4] = make_float4(hv[0], hv[1], hv[2], hv[3]);
            *(float4*)&kl_s[j * KP + d4 * 4] = make_float4(lv[0], lv[1], lv[2], lv[3]);

            float4 vv = *(const float4*)(v + (size_t)(j0 + j) * DV + d4 * 4);
            float va[4] = {vv.x, vv.y, vv.z, vv.w};
#pragma unroll
            for (int e = 0; e < 4; e++)
                vt_s[(d4 * 4 + e) * VP + j] = __uint_as_float(f2tf32(va[e]));
        }
        __syncthreads();

        // S = bias + Q K^T  (3xTF32)
        float s[8][4];
#pragma unroll
        for (int nt = 0; nt < 8; nt++) {
            int di0 = (j0 + nt * 8 + 2 * c) - (ibase + g) + 1056;
            s[nt][0] = bias_s[di0];
            s[nt][1] = bias_s[di0 + 1];
            s[nt][2] = bias_s[di0 - 8];
            s[nt][3] = bias_s[di0 - 7];
#pragma unroll
            for (int kt = 0; kt < 4; kt++) {
                float2 khv = *(const float2*)&kh_s[(nt * 8 + g) * KP + kt * 8 + 2 * c];
                float2 klv = *(const float2*)&kl_s[(nt * 8 + g) * KP + kt * 8 + 2 * c];
                unsigned bh0 = __float_as_uint(khv.x), bh1 = __float_as_uint(khv.y);
                unsigned bl0 = __float_as_uint(klv.x), bl1 = __float_as_uint(klv.y);
                mma_tf32(s[nt], qh[kt], bh0, bh1);
                mma_tf32(s[nt], qh[kt], bl0, bl1);
                mma_tf32(s[nt], ql[kt], bh0, bh1);
            }
        }

        // Online softmax (rows g and g+8; quad shuffles over c).
        float mx0 = -1e30f, mx1 = -1e30f;
#pragma unroll
        for (int nt = 0; nt < 8; nt++) {
            mx0 = fmaxf(mx0, fmaxf(s[nt][0], s[nt][1]));
            mx1 = fmaxf(mx1, fmaxf(s[nt][2], s[nt][3]));
        }
        mx0 = fmaxf(mx0, __shfl_xor_sync(0xffffffffu, mx0, 1));
        mx0 = fmaxf(mx0, __shfl_xor_sync(0xffffffffu, mx0, 2));
        mx1 = fmaxf(mx1, __shfl_xor_sync(0xffffffffu, mx1, 1));
        mx1 = fmaxf(mx1, __shfl_xor_sync(0xffffffffu, mx1, 2));
        float nm0 = fmaxf(m0, mx0);
        float nm1 = fmaxf(m1, mx1);
        float sc0 = __expf(m0 - nm0);
        float sc1 = __expf(m1 - nm1);
        float rs0 = 0.f, rs1 = 0.f;
#pragma unroll
        for (int nt = 0; nt < 8; nt++) {
            s[nt][0] = __expf(s[nt][0] - nm0);
            s[nt][1] = __expf(s[nt][1] - nm0);
            s[nt][2] = __expf(s[nt][2] - nm1);
            s[nt][3] = __expf(s[nt][3] - nm1);
            rs0 += s[nt][0] + s[nt][1];
            rs1 += s[nt][2] + s[nt][3];
        }
        rs0 += __shfl_xor_sync(0xffffffffu, rs0, 1);
        rs0 += __shfl_xor_sync(0xffffffffu, rs0, 2);
        rs1 += __shfl_xor_sync(0xffffffffu, rs1, 1);
        rs1 += __shfl_xor_sync(0xffffffffu, rs1, 2);
        l0 = l0 * sc0 + rs0;
        l1 = l1 * sc1 + rs1;
        m0 = nm0;
        m1 = nm1;
#pragma unroll
        for (int dt = 0; dt < 4; dt++) {
            o[dt][0] *= sc0; o[dt][1] *= sc0;
            o[dt][2] *= sc1; o[dt][3] *= sc1;
        }

        // Convert P to tf32 in place.
#pragma unroll
        for (int nt = 0; nt < 8; nt++)
#pragma unroll
            for (int e = 0; e < 4; e++)
                s[nt][e] = __uint_as_float(f2tf32(s[nt][e]));

        // O += P V   (A-frag order: c0, c2, c1, c3)
#pragma unroll
        for (int dt = 0; dt < 4; dt++) {
#pragma unroll
            for (int jt = 0; jt < 8; jt++) {
                unsigned a[4] = {__float_as_uint(s[jt][0]), __float_as_uint(s[jt][2]),
                                 __float_as_uint(s[jt][1]), __float_as_uint(s[jt][3])};
                float2 vv2 = *(const float2*)&vt_s[(dt * 8 + g) * VP + jt * 8 + 2 * c];
                mma_tf32(o[dt], a, __float_as_uint(vv2.x), __float_as_uint(vv2.y));
            }
        }
    }

    // Normalize and store.
    float inv0 = 1.0f / l0;
    float inv1 = 1.0f / l1;
    float* base0 = g_attn + ((size_t)(b * L + ibase + g)) * (NH * DV) + h * DV;
    float* base1 = base0 + (size_t)8 * (NH * DV);
#pragma unroll
    for (int dt = 0; dt < 4; dt++) {
        *(float2*)&base0[dt * 8 + 2 * c] = make_float2(o[dt][0] * inv0, o[dt][1] * inv0);
        *(float2*)&base1[dt * 8 + 2 * c] = make_float2(o[dt][2] * inv1, o[dt][3] * inv1);
    }
}

// ---------------------------------------------------------------------------
// Kernel 3: FF projection + bias, transposed output (unchanged, known-good).
// ---------------------------------------------------------------------------
__global__ __launch_bounds__(256) void ff_kernel(
    const float* __restrict__ ffw,
    const float* __restrict__ ffb,
    float* __restrict__ out)
{
    __shared__ float As[16][132];
    __shared__ float Ws[16][64];

    const int m0  = blockIdx.x * 128;
    const int n0  = blockIdx.y * 64;
    const int tid = threadIdx.x;
    const int tm  = tid / 16;
    const int tn  = tid % 16;

    float acc[8][4] = {};
    const float* A = g_attn;

    for (int k0 = 0; k0 < NH * DV; k0 += 16) {
#pragma unroll
        for (int it = 0; it < 2; it++) {
            int s  = tid + it * 256;
            int m  = s >> 2;
            int k4 = s & 3;
            float4 val = *(const float4*)&A[(size_t)(m0 + m) * (NH * DV) + k0 + k4 * 4];
            As[k4 * 4 + 0][m] = val.x;
            As[k4 * 4 + 1][m] = val.y;
            As[k4 * 4 + 2][m] = val.z;
            As[k4 * 4 + 3][m] = val.w;
        }
        {
            int kk = tid >> 4;
            int n4 = tid & 15;
            *(float4*)&Ws[kk][n4 * 4] =
                *(const float4*)&ffw[(size_t)(k0 + kk) * OUTC + n0 + n4 * 4];
        }
        __syncthreads();

#pragma unroll
        for (int kk = 0; kk < 16; kk++) {
            float ra[8], rb[4];
            *(float4*)&ra[0] = *(float4*)&As[kk][tm * 8];
            *(float4*)&ra[4] = *(float4*)&As[kk][tm * 8 + 4];
            *(float4*)&rb[0] = *(float4*)&Ws[kk][tn * 4];
#pragma unroll
            for (int i = 0; i < 8; i++)
#pragma unroll
                for (int j = 0; j < 4; j++)
                    acc[i][j] += ra[i] * rb[j];
        }
        __syncthreads();
    }

    const int b  = m0 >> 10;
    const int l0 = m0 & 1023;
#pragma unroll
    for (int j = 0; j < 4; j++) {
        int n = n0 + tn * 4 + j;
        float bias = ffb[n];
        float* dst = out + ((size_t)(b * OUTC + n)) * L + l0 + tm * 8;
        float tmp[8];
#pragma unroll
        for (int i = 0; i < 8; i++) tmp[i] = acc[i][j] + bias;
        *(float4*)&dst[0] = *(float4*)&tmp[0];
        *(float4*)&dst[4] = *(float4*)&tmp[4];
    }
}

// ---------------------------------------------------------------------------
extern "C" void kernel_launch(void* const* d_in, const int* in_sizes, int n_in,
                              void* d_out, int out_size)
{
    const float* x        = (const float*)d_in[0];
    const float* Qw       = (const float*)d_in[1];
    const float* Kw       = (const float*)d_in[2];
    const float* Vw       = (const float*)d_in[3];
    const float* ffw      = (const float*)d_in[4];
    const float* ffb      = (const float*)d_in[5];
    const float* rel_bias = (const float*)d_in[6];
    float* out = (float*)d_out;

    qkv_gemm<<<dim3(L / 128, (NH * DK) / 64, B * 3), 256>>>(x, Qw, Kw, Vw);
    attn_mma<<<dim3(L / 128, B * NH), 256>>>(rel_bias);
    ff_kernel<<<dim3((B * L) / 128, OUTC / 64, 1), 256>>>(ffw, ffb, out);
}

// round 5
// speedup vs baseline: 4.5828x; 1.6944x over previous
#include <cuda_runtime.h>
#include <cuda_bf16.h>

// Problem constants
constexpr int B    = 8;
constexpr int C    = 256;
constexpr int L    = 1024;     // 32*32
constexpr int NH   = 8;
constexpr int DK   = 32;
constexpr int DV   = 32;
constexpr int OUTC = 256;
constexpr int TBL  = 63 * 63;
constexpr int BIAS_STAGE = 2080;  // idx = j - i + 1056 ∈ [33, 2079]

// Scratch (device globals)
__device__ __nv_bfloat16 g_xh[(size_t)B * L * C];   // x^T split  [b][l][c]
__device__ __nv_bfloat16 g_xl[(size_t)B * L * C];
__device__ __nv_bfloat16 g_wh[3 * 256 * 256];       // W^T split  [which][n][c]
__device__ __nv_bfloat16 g_wl[3 * 256 * 256];
__device__ __nv_bfloat16 g_qh[(size_t)B * NH * L * DK];  // [bh][l][d]
__device__ __nv_bfloat16 g_ql[(size_t)B * NH * L * DK];
__device__ __nv_bfloat16 g_kh[(size_t)B * NH * L * DK];
__device__ __nv_bfloat16 g_kl[(size_t)B * NH * L * DK];
__device__ float g_vt[(size_t)B * NH * DV * L];          // [bh][d][l], tf32-rounded
__device__ float g_attn[(size_t)B * L * NH * DV];        // [b][l][h*DV+d]

// ---------------------------------------------------------------------------
// helpers
// ---------------------------------------------------------------------------
__device__ __forceinline__ unsigned f2tf32(float x) {
    unsigned r;
    asm("cvt.rna.tf32.f32 %0, %1;" : "=r"(r) : "f"(x));
    return r;
}
__device__ __forceinline__ float tf32r(float x) { return __uint_as_float(f2tf32(x)); }

__device__ __forceinline__ void mma_tf32(float c[4], const unsigned a[4],
                                         unsigned b0, unsigned b1) {
    asm("mma.sync.aligned.m16n8k8.row.col.f32.tf32.tf32.f32 "
        "{%0,%1,%2,%3}, {%4,%5,%6,%7}, {%8,%9}, {%0,%1,%2,%3};"
        : "+f"(c[0]), "+f"(c[1]), "+f"(c[2]), "+f"(c[3])
        : "r"(a[0]), "r"(a[1]), "r"(a[2]), "r"(a[3]), "r"(b0), "r"(b1));
}
__device__ __forceinline__ void mma_bf16(float c[4], const unsigned a[4],
                                         unsigned b0, unsigned b1) {
    asm("mma.sync.aligned.m16n8k16.row.col.f32.bf16.bf16.f32 "
        "{%0,%1,%2,%3}, {%4,%5,%6,%7}, {%8,%9}, {%0,%1,%2,%3};"
        : "+f"(c[0]), "+f"(c[1]), "+f"(c[2]), "+f"(c[3])
        : "r"(a[0]), "r"(a[1]), "r"(a[2]), "r"(a[3]), "r"(b0), "r"(b1));
}
__device__ __forceinline__ void ldsm4(unsigned r[4], unsigned addr) {
    asm volatile("ldmatrix.sync.aligned.m8n8.x4.shared.b16 {%0,%1,%2,%3}, [%4];"
                 : "=r"(r[0]), "=r"(r[1]), "=r"(r[2]), "=r"(r[3]) : "r"(addr));
}
__device__ __forceinline__ unsigned smem_u32(const void* p) {
    return (unsigned)__cvta_generic_to_shared(p);
}
__device__ __forceinline__ void bsplit2(float v0, float v1, unsigned& hi, unsigned& lo) {
    __nv_bfloat16 h0 = __float2bfloat16(v0);
    __nv_bfloat16 h1 = __float2bfloat16(v1);
    __nv_bfloat16 l0 = __float2bfloat16(v0 - __bfloat162float(h0));
    __nv_bfloat16 l1 = __float2bfloat16(v1 - __bfloat162float(h1));
    hi = (unsigned)__bfloat16_as_ushort(h0) | ((unsigned)__bfloat16_as_ushort(h1) << 16);
    lo = (unsigned)__bfloat16_as_ushort(l0) | ((unsigned)__bfloat16_as_ushort(l1) << 16);
}

// ---------------------------------------------------------------------------
// Kernel 0: prep — transpose + bf16 hi/lo split of x (→[b][l][c]) and W (→[n][c]).
// t pitch 36 floats (144 B) keeps float4 stores 16B-aligned.
// ---------------------------------------------------------------------------
__global__ __launch_bounds__(256) void prep_kernel(
    const float* __restrict__ x,  const float* __restrict__ Qw,
    const float* __restrict__ Kw, const float* __restrict__ Vw)
{
    __shared__ float t[32][36];
    const int bid = blockIdx.x;
    const int tid = threadIdx.x;

    if (bid < 2048) {                 // x part: 256 tiles per batch
        const int b  = bid >> 8;
        const int r  = bid & 255;
        const int ct = r >> 5;        // c tile (8)
        const int lt = r & 31;        // l tile (32)
        {
            int i = tid >> 3, j4 = tid & 7;
            *(float4*)&t[i][j4 * 4] =
                *(const float4*)&x[((size_t)b * C + ct * 32 + i) * L + lt * 32 + j4 * 4];
        }
        __syncthreads();
#pragma unroll
        for (int it = 0; it < 2; it++) {
            int s = tid + it * 256;
            int l = s >> 4, c2 = (s & 15) * 2;
            unsigned hi, lo;
            bsplit2(t[c2][l], t[c2 + 1][l], hi, lo);
            size_t o = ((size_t)b * L + lt * 32 + l) * C + ct * 32 + c2;
            *(unsigned*)&g_xh[o] = hi;
            *(unsigned*)&g_xl[o] = lo;
        }
    } else {                          // W part: 64 tiles per matrix
        const int r     = bid - 2048;
        const int which = r >> 6;
        const int rr    = r & 63;
        const int ct    = rr >> 3;    // c tile (8)
        const int nt    = rr & 7;     // n tile (8)
        const float* Wm = (which == 0) ? Qw : (which == 1) ? Kw : Vw;
        {
            int i = tid >> 3, j4 = tid & 7;
            *(float4*)&t[i][j4 * 4] =
                *(const float4*)&Wm[((size_t)(ct * 32 + i)) * 256 + nt * 32 + j4 * 4];
        }
        __syncthreads();
#pragma unroll
        for (int it = 0; it < 2; it++) {
            int s = tid + it * 256;
            int n = s >> 4, c2 = (s & 15) * 2;
            unsigned hi, lo;
            bsplit2(t[c2][n], t[c2 + 1][n], hi, lo);
            size_t o = ((size_t)which * 256 + nt * 32 + n) * 256 + ct * 32 + c2;
            *(unsigned*)&g_wh[o] = hi;
            *(unsigned*)&g_wl[o] = lo;
        }
    }
}

// ---------------------------------------------------------------------------
// Kernel 1: QKV projections, bf16x3 mma.  out = x^T @ W per (b, which).
// Block 128x64, 8 warps (4x2), warp tile 32x32.
// Q/K stored as bf16 hi/lo [bh][l][d]; V stored tf32-rounded transposed [bh][d][l].
// ---------------------------------------------------------------------------
__global__ __launch_bounds__(256) void qkv_mma()
{
    constexpr int AP = 40;   // bf16 pitch (80B rows, 16B-aligned)
    __shared__ __nv_bfloat16 Ah[128 * AP], Al[128 * AP];
    __shared__ __nv_bfloat16 Bh[64 * AP],  Bl[64 * AP];

    const int bz    = blockIdx.z;
    const int b     = bz / 3;
    const int which = bz % 3;
    const __nv_bfloat16* Asrc_h = g_xh + (size_t)b * L * C;
    const __nv_bfloat16* Asrc_l = g_xl + (size_t)b * L * C;
    const __nv_bfloat16* Bsrc_h = g_wh + (size_t)which * 256 * 256;
    const __nv_bfloat16* Bsrc_l = g_wl + (size_t)which * 256 * 256;

    const int m0   = blockIdx.x * 128;
    const int n0   = blockIdx.y * 64;
    const int tid  = threadIdx.x;
    const int warp = tid >> 5;
    const int lane = tid & 31;
    const int gq   = lane >> 2;
    const int cq   = lane & 3;
    const int wm   = warp >> 1;
    const int wn   = warp & 1;
    const int lt   = lane >> 3;
    const int lr   = lane & 7;

    float acc[2][4][4] = {};

    for (int k0 = 0; k0 < 256; k0 += 32) {
#pragma unroll
        for (int it = 0; it < 2; it++) {
            int s = tid + it * 256;
            int m = s >> 2, c8 = (s & 3) * 8;
            *(uint4*)&Ah[m * AP + c8] = *(const uint4*)&Asrc_h[(size_t)(m0 + m) * C + k0 + c8];
            *(uint4*)&Al[m * AP + c8] = *(const uint4*)&Asrc_l[(size_t)(m0 + m) * C + k0 + c8];
        }
        {
            int n = tid >> 2, c8 = (tid & 3) * 8;
            *(uint4*)&Bh[n * AP + c8] = *(const uint4*)&Bsrc_h[(size_t)(n0 + n) * 256 + k0 + c8];
            *(uint4*)&Bl[n * AP + c8] = *(const uint4*)&Bsrc_l[(size_t)(n0 + n) * 256 + k0 + c8];
        }
        __syncthreads();

#pragma unroll
        for (int kc = 0; kc < 32; kc += 16) {
            unsigned ah[2][4], al[2][4];
#pragma unroll
            for (int mt = 0; mt < 2; mt++) {
                int row = wm * 32 + mt * 16 + (lt & 1) * 8 + lr;
                int col = kc + (lt >> 1) * 8;
                ldsm4(ah[mt], smem_u32(&Ah[row * AP + col]));
                ldsm4(al[mt], smem_u32(&Al[row * AP + col]));
            }
#pragma unroll
            for (int np = 0; np < 2; np++) {
                unsigned bhf[4], blf[4];
                int row = wn * 32 + np * 16 + (lt >> 1) * 8 + lr;
                int col = kc + (lt & 1) * 8;
                ldsm4(bhf, smem_u32(&Bh[row * AP + col]));
                ldsm4(blf, smem_u32(&Bl[row * AP + col]));
#pragma unroll
                for (int mt = 0; mt < 2; mt++)
#pragma unroll
                    for (int sub = 0; sub < 2; sub++) {
                        float* ca = acc[mt][np * 2 + sub];
                        mma_bf16(ca, ah[mt], bhf[sub * 2], bhf[sub * 2 + 1]);
                        mma_bf16(ca, ah[mt], blf[sub * 2], blf[sub * 2 + 1]);
                        mma_bf16(ca, al[mt], bhf[sub * 2], bhf[sub * 2 + 1]);
                    }
            }
        }
        __syncthreads();
    }

    // epilogue
    const int h = (n0 >> 5) + wn;
    if (which < 2) {
        __nv_bfloat16* oh = ((which == 0) ? g_qh : g_kh) + (size_t)(b * NH + h) * L * DK;
        __nv_bfloat16* ol = ((which == 0) ? g_ql : g_kl) + (size_t)(b * NH + h) * L * DK;
#pragma unroll
        for (int mt = 0; mt < 2; mt++)
#pragma unroll
            for (int nt = 0; nt < 4; nt++) {
                int d = nt * 8 + cq * 2;
#pragma unroll
                for (int rs = 0; rs < 2; rs++) {
                    int gm = m0 + wm * 32 + mt * 16 + gq + rs * 8;
                    unsigned hi, lo;
                    bsplit2(acc[mt][nt][rs * 2], acc[mt][nt][rs * 2 + 1], hi, lo);
                    *(unsigned*)&oh[(size_t)gm * DK + d] = hi;
                    *(unsigned*)&ol[(size_t)gm * DK + d] = lo;
                }
            }
    } else {
        float* ov = g_vt + (size_t)(b * NH + h) * DV * L;
#pragma unroll
        for (int mt = 0; mt < 2; mt++)
#pragma unroll
            for (int nt = 0; nt < 4; nt++)
#pragma unroll
                for (int rs = 0; rs < 2; rs++) {
                    int gm = m0 + wm * 32 + mt * 16 + gq + rs * 8;
                    int d  = nt * 8 + cq * 2;
                    ov[(size_t)d * L + gm]       = tf32r(acc[mt][nt][rs * 2]);
                    ov[(size_t)(d + 1) * L + gm] = tf32r(acc[mt][nt][rs * 2 + 1]);
                }
    }
}

// ---------------------------------------------------------------------------
// Kernel 2: flash attention. QK^T = bf16x3 (pre-split q,k); PV = tf32.
// Br=128 (8 warps x 16 rows), Bc=64. Toeplitz bias from smem.
// VP=68 keeps float4 staging stores 16B-aligned.
// ---------------------------------------------------------------------------
__global__ __launch_bounds__(256) void attn_mma(const float* __restrict__ rel_bias)
{
    constexpr int KP = 40;   // bf16 pitch
    constexpr int VP = 68;   // fp32 pitch (272B, 16B-aligned)
    __shared__ float bias_s[BIAS_STAGE];
    __shared__ __align__(16) char buf[20480];
    __nv_bfloat16* kh_s = (__nv_bfloat16*)buf;
    __nv_bfloat16* kl_s = kh_s + 64 * KP;
    float*         vt_s = (float*)(buf + 2 * 64 * KP * 2);   // 32*VP*4 = 8704 B
    __nv_bfloat16* qh_s = (__nv_bfloat16*)buf;               // overlay (pre-loop only)
    __nv_bfloat16* ql_s = qh_s + 128 * KP;

    const int bh = blockIdx.y;
    const int h  = bh & 7;
    const int b  = bh >> 3;
    const __nv_bfloat16* qh_g = g_qh + (size_t)bh * L * DK;
    const __nv_bfloat16* ql_g = g_ql + (size_t)bh * L * DK;
    const __nv_bfloat16* kh_g = g_kh + (size_t)bh * L * DK;
    const __nv_bfloat16* kl_g = g_kl + (size_t)bh * L * DK;
    const float*         vt_g = g_vt + (size_t)bh * DV * L;

    const int tid  = threadIdx.x;
    const int warp = tid >> 5;
    const int lane = tid & 31;
    const int g    = lane >> 2;
    const int c    = lane & 3;
    const int lt   = lane >> 3;
    const int lr   = lane & 7;
    const int i0   = blockIdx.x * 128;

    for (int i = tid; i < BIAS_STAGE; i += 256)
        bias_s[i] = rel_bias[(size_t)h * TBL + i];

    // stage q, pull frags to registers
#pragma unroll
    for (int it = 0; it < 2; it++) {
        int s = tid + it * 256;
        int row = s >> 2, c8 = (s & 3) * 8;
        *(uint4*)&qh_s[row * KP + c8] = *(const uint4*)&qh_g[(size_t)(i0 + row) * DK + c8];
        *(uint4*)&ql_s[row * KP + c8] = *(const uint4*)&ql_g[(size_t)(i0 + row) * DK + c8];
    }
    __syncthreads();
    unsigned qh[2][4], ql[2][4];
#pragma unroll
    for (int kc = 0; kc < 2; kc++) {
        int row = warp * 16 + (lt & 1) * 8 + lr;
        int col = kc * 16 + (lt >> 1) * 8;
        ldsm4(qh[kc], smem_u32(&qh_s[row * KP + col]));
        ldsm4(ql[kc], smem_u32(&ql_s[row * KP + col]));
    }

    float m0 = -1e30f, m1 = -1e30f, l0 = 0.f, l1 = 0.f;
    float o[4][4] = {};

    for (int j0 = 0; j0 < L; j0 += 64) {
        __syncthreads();
        {
            int j = tid >> 2, c8 = (tid & 3) * 8;
            *(uint4*)&kh_s[j * KP + c8] = *(const uint4*)&kh_g[(size_t)(j0 + j) * DK + c8];
            *(uint4*)&kl_s[j * KP + c8] = *(const uint4*)&kl_g[(size_t)(j0 + j) * DK + c8];
        }
#pragma unroll
        for (int it = 0; it < 2; it++) {
            int s = tid + it * 256;
            int d = s >> 4, j4 = (s & 15) * 4;
            *(float4*)&vt_s[d * VP + j4] = *(const float4*)&vt_g[(size_t)d * L + j0 + j4];
        }
        __syncthreads();

        // S = bias + Q K^T (bf16x3)
        float s[8][4];
#pragma unroll
        for (int nt = 0; nt < 8; nt++) {
            int di0 = (j0 + nt * 8 + 2 * c) - (i0 + warp * 16 + g) + 1056;
            s[nt][0] = bias_s[di0];
            s[nt][1] = bias_s[di0 + 1];
            s[nt][2] = bias_s[di0 - 8];
            s[nt][3] = bias_s[di0 - 7];
        }
#pragma unroll
        for (int kc = 0; kc < 2; kc++)
#pragma unroll
            for (int np = 0; np < 4; np++) {
                unsigned bhf[4], blf[4];
                int row = np * 16 + (lt >> 1) * 8 + lr;
                int col = kc * 16 + (lt & 1) * 8;
                ldsm4(bhf, smem_u32(&kh_s[row * KP + col]));
                ldsm4(blf, smem_u32(&kl_s[row * KP + col]));
#pragma unroll
                for (int sub = 0; sub < 2; sub++) {
                    float* sp = s[np * 2 + sub];
                    mma_bf16(sp, qh[kc], bhf[sub * 2], bhf[sub * 2 + 1]);
                    mma_bf16(sp, qh[kc], blf[sub * 2], blf[sub * 2 + 1]);
                    mma_bf16(sp, ql[kc], bhf[sub * 2], bhf[sub * 2 + 1]);
                }
            }

        // online softmax
        float mx0 = -1e30f, mx1 = -1e30f;
#pragma unroll
        for (int nt = 0; nt < 8; nt++) {
            mx0 = fmaxf(mx0, fmaxf(s[nt][0], s[nt][1]));
            mx1 = fmaxf(mx1, fmaxf(s[nt][2], s[nt][3]));
        }
        mx0 = fmaxf(mx0, __shfl_xor_sync(0xffffffffu, mx0, 1));
        mx0 = fmaxf(mx0, __shfl_xor_sync(0xffffffffu, mx0, 2));
        mx1 = fmaxf(mx1, __shfl_xor_sync(0xffffffffu, mx1, 1));
        mx1 = fmaxf(mx1, __shfl_xor_sync(0xffffffffu, mx1, 2));
        float nm0 = fmaxf(m0, mx0);
        float nm1 = fmaxf(m1, mx1);
        float sc0 = __expf(m0 - nm0);
        float sc1 = __expf(m1 - nm1);
        float rs0 = 0.f, rs1 = 0.f;
#pragma unroll
        for (int nt = 0; nt < 8; nt++) {
            s[nt][0] = __expf(s[nt][0] - nm0);
            s[nt][1] = __expf(s[nt][1] - nm0);
            s[nt][2] = __expf(s[nt][2] - nm1);
            s[nt][3] = __expf(s[nt][3] - nm1);
            rs0 += s[nt][0] + s[nt][1];
            rs1 += s[nt][2] + s[nt][3];
        }
        rs0 += __shfl_xor_sync(0xffffffffu, rs0, 1);
        rs0 += __shfl_xor_sync(0xffffffffu, rs0, 2);
        rs1 += __shfl_xor_sync(0xffffffffu, rs1, 1);
        rs1 += __shfl_xor_sync(0xffffffffu, rs1, 2);
        l0 = l0 * sc0 + rs0;
        l1 = l1 * sc1 + rs1;
        m0 = nm0;
        m1 = nm1;
#pragma unroll
        for (int dt = 0; dt < 4; dt++) {
            o[dt][0] *= sc0; o[dt][1] *= sc0;
            o[dt][2] *= sc1; o[dt][3] *= sc1;
        }
#pragma unroll
        for (int nt = 0; nt < 8; nt++)
#pragma unroll
            for (int e = 0; e < 4; e++)
                s[nt][e] = tf32r(s[nt][e]);

        // O += P V (tf32, lane-consistent k-permutation)
#pragma unroll
        for (int dt = 0; dt < 4; dt++)
#pragma unroll
            for (int jt = 0; jt < 8; jt++) {
                unsigned a[4] = {__float_as_uint(s[jt][0]), __float_as_uint(s[jt][2]),
                                 __float_as_uint(s[jt][1]), __float_as_uint(s[jt][3])};
                float2 vv2 = *(const float2*)&vt_s[(dt * 8 + g) * VP + jt * 8 + 2 * c];
                mma_tf32(o[dt], a, __float_as_uint(vv2.x), __float_as_uint(vv2.y));
            }
    }

    float inv0 = 1.0f / l0;
    float inv1 = 1.0f / l1;
    float* base0 = g_attn + ((size_t)(b * L + i0 + warp * 16 + g)) * (NH * DV) + h * DV;
    float* base1 = base0 + (size_t)8 * (NH * DV);
#pragma unroll
    for (int dt = 0; dt < 4; dt++) {
        *(float2*)&base0[dt * 8 + 2 * c] = make_float2(o[dt][0] * inv0, o[dt][1] * inv0);
        *(float2*)&base1[dt * 8 + 2 * c] = make_float2(o[dt][2] * inv1, o[dt][3] * inv1);
    }
}

// ---------------------------------------------------------------------------
// Kernel 3: FF projection, tf32 mma, fused bias + transposed store.
// Block 128x64, 8 warps (4x2), warp tile 32x32. AP=36 / WP=34 for alignment.
// ---------------------------------------------------------------------------
__global__ __launch_bounds__(256) void ff_mma(
    const float* __restrict__ ffw,
    const float* __restrict__ ffb,
    float* __restrict__ out)
{
    constexpr int AP = 36, WP = 34;
    __shared__ float As[128 * AP];
    __shared__ float Ws[64 * WP];

    const int m0   = blockIdx.x * 128;
    const int n0   = blockIdx.y * 64;
    const int tid  = threadIdx.x;
    const int warp = tid >> 5;
    const int lane = tid & 31;
    const int g    = lane >> 2;
    const int c    = lane & 3;
    const int wm   = warp >> 1;
    const int wn   = warp & 1;

    float acc[2][4][4] = {};

    for (int k0 = 0; k0 < 256; k0 += 32) {
#pragma unroll
        for (int it = 0; it < 4; it++) {
            int s = tid + it * 256;
            int m = s >> 3, k4 = (s & 7) * 4;
            float4 v = *(const float4*)&g_attn[(size_t)(m0 + m) * 256 + k0 + k4];
            v.x = tf32r(v.x); v.y = tf32r(v.y); v.z = tf32r(v.z); v.w = tf32r(v.w);
            *(float4*)&As[m * AP + k4] = v;
        }
#pragma unroll
        for (int it = 0; it < 2; it++) {
            int s = tid + it * 256;
            int k = s >> 4, n4 = (s & 15) * 4;
            float4 v = *(const float4*)&ffw[(size_t)(k0 + k) * 256 + n0 + n4];
            Ws[(n4 + 0) * WP + k] = tf32r(v.x);
            Ws[(n4 + 1) * WP + k] = tf32r(v.y);
            Ws[(n4 + 2) * WP + k] = tf32r(v.z);
            Ws[(n4 + 3) * WP + k] = tf32r(v.w);
        }
        __syncthreads();

#pragma unroll
        for (int kt = 0; kt < 4; kt++) {
            unsigned a[2][4];
#pragma unroll
            for (int mt = 0; mt < 2; mt++) {
                int mr = wm * 32 + mt * 16;
                float2 f0 = *(const float2*)&As[(mr + g) * AP + kt * 8 + 2 * c];
                float2 f1 = *(const float2*)&As[(mr + 8 + g) * AP + kt * 8 + 2 * c];
                a[mt][0] = __float_as_uint(f0.x);
                a[mt][1] = __float_as_uint(f1.x);
                a[mt][2] = __float_as_uint(f0.y);
                a[mt][3] = __float_as_uint(f1.y);
            }
#pragma unroll
            for (int nt = 0; nt < 4; nt++) {
                float2 bv = *(const float2*)&Ws[(wn * 32 + nt * 8 + g) * WP + kt * 8 + 2 * c];
#pragma unroll
                for (int mt = 0; mt < 2; mt++)
                    mma_tf32(acc[mt][nt], a[mt],
                             __float_as_uint(bv.x), __float_as_uint(bv.y));
            }
        }
        __syncthreads();
    }

    const int bb  = m0 >> 10;
    const int l00 = m0 & 1023;
#pragma unroll
    for (int nt = 0; nt < 4; nt++)
#pragma unroll
        for (int e = 0; e < 2; e++) {
            int gn = n0 + wn * 32 + nt * 8 + 2 * c + e;
            float bias = ffb[gn];
            float* dst = out + ((size_t)(bb * OUTC + gn)) * L + l00 + wm * 32;
#pragma unroll
            for (int mt = 0; mt < 2; mt++)
#pragma unroll
                for (int rs = 0; rs < 2; rs++)
                    dst[mt * 16 + rs * 8 + g] = acc[mt][nt][rs * 2 + e] + bias;
        }
}

// ---------------------------------------------------------------------------
extern "C" void kernel_launch(void* const* d_in, const int* in_sizes, int n_in,
                              void* d_out, int out_size)
{
    const float* x        = (const float*)d_in[0];
    const float* Qw       = (const float*)d_in[1];
    const float* Kw       = (const float*)d_in[2];
    const float* Vw       = (const float*)d_in[3];
    const float* ffw      = (const float*)d_in[4];
    const float* ffb      = (const float*)d_in[5];
    const float* rel_bias = (const float*)d_in[6];
    float* out = (float*)d_out;

    prep_kernel<<<2048 + 192, 256>>>(x, Qw, Kw, Vw);
    qkv_mma<<<dim3(L / 128, 4, B * 3), 256>>>();
    attn_mma<<<dim3(L / 128, B * NH), 256>>>(rel_bias);
    ff_mma<<<dim3((B * L) / 128, OUTC / 64, 1), 256>>>(ffw, ffb, out);
}